// round 6
// baseline (speedup 1.0000x reference)
#include <cuda_runtime.h>
#include <cuda_bf16.h>
#include <cstdint>
#include <math.h>

// ---------------------------------------------------------------------------
// MaskedHeteroGAT: only edge type t = T-1 feeds the scalar output through the
// GAT path. Pipeline (t = T-1 only):
//   hs1 = (x_src*mask) @ W1_src[t];  hd1 = (x_tgt[t]*mask) @ W1_dst[t]
//   h1  = relu(GATv2(hs1, hd1, a1[t]))
//   hs2 = (x_src*mask) @ W2_src[t];  hd2 = h1 @ W2_dst[t]
//   h2  = GATv2(hs2, hd2, a2[t])
//   out = sigmoid( mean(h2).Wcls[0:256] + mean_e(edge_attr).Wcls[256:] + b )
// GEMMs: implicit-tf32 mma.sync (raw fp32 bits, HW truncation) + cp.async.
// Attention: warp per (dst, head-pair), shfl-broadcast index prefetch, MLP=4.
// ---------------------------------------------------------------------------

#define NN_MAX 20000
#define EE_MAX 100000
#define HCV 256

__device__ float g_hs1[(size_t)NN_MAX * HCV];
__device__ float g_hd1[(size_t)NN_MAX * HCV];
__device__ float g_h1 [(size_t)NN_MAX * HCV];
__device__ float g_hs2[(size_t)NN_MAX * HCV];
__device__ float g_hd2[(size_t)NN_MAX * HCV];
__device__ float g_h2 [(size_t)NN_MAX * HCV];
__device__ int   g_rowoff[NN_MAX + 1];
__device__ int   g_cursor[NN_MAX];
__device__ int   g_psrc [EE_MAX];
__device__ float g_pmask[EE_MAX];

struct ZeroRegion {
    int   counts[NN_MAX];
    float csum[HCV];
    float agg[16];
};
__device__ ZeroRegion g_zero;

// ---------------- helpers --------------------------------------------------
__device__ __forceinline__ void cp16(void* smem_dst, const void* gmem_src, int sz) {
    uint32_t d = (uint32_t)__cvta_generic_to_shared(smem_dst);
    asm volatile("cp.async.cg.shared.global [%0], [%1], 16, %2;\n"
                 :: "r"(d), "l"(gmem_src), "r"(sz));
}
__device__ __forceinline__ void cp_commit() { asm volatile("cp.async.commit_group;\n"); }
__device__ __forceinline__ void cp_wait0()  { asm volatile("cp.async.wait_group 0;\n"); }

#define MMA_TF32(d, a, b) \
    asm volatile("mma.sync.aligned.m16n8k8.row.col.f32.tf32.tf32.f32 " \
                 "{%0,%1,%2,%3},{%4,%5,%6,%7},{%8,%9},{%0,%1,%2,%3};" \
                 : "+f"((d)[0]), "+f"((d)[1]), "+f"((d)[2]), "+f"((d)[3]) \
                 : "r"((a)[0]), "r"((a)[1]), "r"((a)[2]), "r"((a)[3]), \
                   "r"((b)[0]), "r"((b)[1]))

// ---------------- edge_attr means (parallel, atomic) ------------------------
__global__ void edge_mean_kernel(const float* __restrict__ ea, float* __restrict__ agg, int E) {
    const int SL = 32;
    int t = blockIdx.x / SL, sl = blockIdx.x % SL;
    const float* p = ea + (size_t)t * E;
    int per = (E + SL - 1) / SL;
    int lo = sl * per, hi = min(E, lo + per);
    float acc = 0.f;
    for (int i = lo + threadIdx.x; i < hi; i += blockDim.x) acc += p[i];
#pragma unroll
    for (int off = 16; off; off >>= 1) acc += __shfl_xor_sync(0xffffffffu, acc, off);
    __shared__ float s[8];
    if ((threadIdx.x & 31) == 0) s[threadIdx.x >> 5] = acc;
    __syncthreads();
    if (threadIdx.x == 0) {
        float v = 0.f;
        for (int w = 0; w < (int)(blockDim.x >> 5); w++) v += s[w];
        atomicAdd(&agg[t], v / (float)E);
    }
}

// ---------------- CSR build ------------------------------------------------
__global__ void hist_kernel(const int* __restrict__ dst, int* __restrict__ counts, int E) {
    int e = blockIdx.x * blockDim.x + threadIdx.x;
    if (e < E) atomicAdd(&counts[dst[e]], 1);
}

__global__ void scan_kernel(const int* __restrict__ counts, int* __restrict__ rowoff,
                            int* __restrict__ cursor, int N) {
    const int CH = (N + 1023) / 1024;
    __shared__ int s[1024];
    int t = threadIdx.x;
    int base = t * CH;
    int local = 0;
    for (int i = 0; i < CH; i++) {
        int idx = base + i;
        if (idx < N) local += counts[idx];
    }
    s[t] = local;
    __syncthreads();
    for (int o = 1; o < 1024; o <<= 1) {
        int v = s[t];
        int add = (t >= o) ? s[t - o] : 0;
        __syncthreads();
        s[t] = v + add;
        __syncthreads();
    }
    int run = (t == 0) ? 0 : s[t - 1];
    for (int i = 0; i < CH; i++) {
        int idx = base + i;
        if (idx < N) {
            rowoff[idx] = run;
            cursor[idx] = run;
            run += counts[idx];
        }
    }
    if (t == 1023) rowoff[N] = s[1023];
}

__global__ void scatter_kernel(const int* __restrict__ src, const int* __restrict__ dst,
                               const float* __restrict__ emask, int* __restrict__ cursor,
                               int* __restrict__ psrc, float* __restrict__ pmask, int E) {
    int e = blockIdx.x * blockDim.x + threadIdx.x;
    if (e < E) {
        int p = atomicAdd(&cursor[dst[e]], 1);
        psrc[p]  = src[e];
        pmask[p] = emask[e];
    }
}

// ---------------- implicit-TF32 tensor-core GEMM ---------------------------
// Raw fp32 bits fed to mma.tf32 (HW truncates mantissa; no cvt instructions).
__device__ __forceinline__
void gemm_tile(const float* __restrict__ A, const float* __restrict__ B,
               float* __restrict__ C, const float* __restrict__ rowScale,
               int M, int K, int bm, int bn,
               float (*As)[128][20], float (*Bs)[16][136]) {
    const int tid = threadIdx.x;
    const int warp = tid >> 5, lane = tid & 31;
    const int wm = (warp & 1) * 64;
    const int wn = (warp >> 1) * 32;
    const int g = lane >> 2, tig = lane & 3;

    float acc[4][4][4];
#pragma unroll
    for (int i = 0; i < 4; i++)
#pragma unroll
        for (int j = 0; j < 4; j++)
#pragma unroll
            for (int k = 0; k < 4; k++) acc[i][j][k] = 0.f;

    const int arow = tid >> 1;
    const int akb = (tid & 1) * 8;
    const bool aval = (bm + arow) < M;
    const float* abase = A + (size_t)(bm + arow) * K + akb;
    const int ntiles = K / 16;

    {
        cp16(&As[0][arow][akb],     abase,     aval ? 16 : 0);
        cp16(&As[0][arow][akb + 4], abase + 4, aval ? 16 : 0);
#pragma unroll
        for (int i = 0; i < 2; i++) {
            int ch = tid + i * 256;
            int kk = ch >> 5, nv = ch & 31;
            cp16(&Bs[0][kk][nv * 4], B + (size_t)kk * HCV + bn + nv * 4, 16);
        }
        cp_commit();
    }

    for (int t = 0; t < ntiles; t++) {
        cp_wait0();
        __syncthreads();
        if (t + 1 < ntiles) {
            int s = (t + 1) & 1;
            int k0 = (t + 1) * 16;
            cp16(&As[s][arow][akb],     abase + k0,     aval ? 16 : 0);
            cp16(&As[s][arow][akb + 4], abase + k0 + 4, aval ? 16 : 0);
#pragma unroll
            for (int i = 0; i < 2; i++) {
                int ch = tid + i * 256;
                int kk = ch >> 5, nv = ch & 31;
                cp16(&Bs[s][kk][nv * 4], B + (size_t)(k0 + kk) * HCV + bn + nv * 4, 16);
            }
            cp_commit();
        }
        const int s = t & 1;
#pragma unroll
        for (int ks = 0; ks < 2; ks++) {
            const int kb = ks * 8;
            uint32_t af[4][4], bf[4][2];
#pragma unroll
            for (int mt = 0; mt < 4; mt++) {
                int r0 = wm + mt * 16 + g;
                af[mt][0] = __float_as_uint(As[s][r0][kb + tig]);
                af[mt][1] = __float_as_uint(As[s][r0 + 8][kb + tig]);
                af[mt][2] = __float_as_uint(As[s][r0][kb + tig + 4]);
                af[mt][3] = __float_as_uint(As[s][r0 + 8][kb + tig + 4]);
            }
#pragma unroll
            for (int nt = 0; nt < 4; nt++) {
                int c0 = wn + nt * 8 + g;
                bf[nt][0] = __float_as_uint(Bs[s][kb + tig][c0]);
                bf[nt][1] = __float_as_uint(Bs[s][kb + tig + 4][c0]);
            }
#pragma unroll
            for (int mt = 0; mt < 4; mt++)
#pragma unroll
                for (int nt = 0; nt < 4; nt++)
                    MMA_TF32(acc[mt][nt], af[mt], bf[nt]);
        }
        __syncthreads();
    }

#pragma unroll
    for (int mt = 0; mt < 4; mt++) {
        int row0 = bm + wm + mt * 16 + g;
        int row1 = row0 + 8;
        float s0 = 1.f, s1 = 1.f;
        if (rowScale) {
            if (row0 < M) s0 = rowScale[row0];
            if (row1 < M) s1 = rowScale[row1];
        }
#pragma unroll
        for (int nt = 0; nt < 4; nt++) {
            int col = bn + wn + nt * 8 + tig * 2;
            if (row0 < M) {
                float2 v = make_float2(acc[mt][nt][0] * s0, acc[mt][nt][1] * s0);
                *(float2*)(C + (size_t)row0 * HCV + col) = v;
            }
            if (row1 < M) {
                float2 v = make_float2(acc[mt][nt][2] * s1, acc[mt][nt][3] * s1);
                *(float2*)(C + (size_t)row1 * HCV + col) = v;
            }
        }
    }
}

__global__ __launch_bounds__(256, 2)
void gemm_tf32_kernel(const float* __restrict__ A, const float* __restrict__ B,
                      float* __restrict__ C, const float* __restrict__ rowScale,
                      int M, int K) {
    __shared__ float As[2][128][20];
    __shared__ float Bs[2][16][136];
    gemm_tile(A, B, C, rowScale, M, K, blockIdx.x * 128, blockIdx.y * 128, As, Bs);
}

// fused triple GEMM: z=0 -> {hs1 (y=0,1), hs2 (y=2,3)} from A0; z=1 -> hd1 (y=0,1)
__global__ __launch_bounds__(256, 2)
void gemm3_kernel(const float* __restrict__ A0, const float* __restrict__ B0a,
                  const float* __restrict__ B0b, float* __restrict__ C0a,
                  float* __restrict__ C0b,
                  const float* __restrict__ A1, const float* __restrict__ B1,
                  float* __restrict__ C1,
                  const float* __restrict__ rowScale, int M, int K) {
    __shared__ float As[2][128][20];
    __shared__ float Bs[2][16][136];
    const float *A, *B;
    float* C;
    int bn;
    if (blockIdx.z == 0) {
        A = A0;
        if (blockIdx.y < 2) { B = B0a; C = C0a; bn = blockIdx.y * 128; }
        else                { B = B0b; C = C0b; bn = (blockIdx.y - 2) * 128; }
    } else {
        if (blockIdx.y >= 2) return;
        A = A1; B = B1; C = C1; bn = blockIdx.y * 128;
    }
    gemm_tile(A, B, C, rowScale, M, K, blockIdx.x * 128, bn, As, Bs);
}

// ---------------- GATv2 attention: one warp per (dst, head-pair) ------------
// Index prefetch: lanes cooperatively load up to 32 (idx,mask) pairs in one
// coalesced access, then shfl-broadcast; hs row gathers batched 4-deep (MLP=4).
__global__ void attn_kernel(const float* __restrict__ hs, const float* __restrict__ hd,
                            const float* __restrict__ avec,
                            const int* __restrict__ psrc, const float* __restrict__ pmask,
                            const int* __restrict__ rowoff, float* __restrict__ out,
                            int Nt, int doRelu) {
    int warp = threadIdx.x >> 5, lane = threadIdx.x & 31;
    int gw = blockIdx.x * (blockDim.x >> 5) + warp;
    int dst = gw >> 1, hp = gw & 1;
    if (dst >= Nt) return;
    int beg = rowoff[dst], end = rowoff[dst + 1];
    int deg = end - beg;

    const float4* hs4 = (const float4*)hs;
    const int chunk = hp * 32 + lane;
    float4 hdv = ((const float4*)hd)[(size_t)dst * 64 + chunk];
    float4 av  = ((const float4*)avec)[chunk];

    float4 num = make_float4(0.f, 0.f, 0.f, 0.f);
    float den = 0.f;

    for (int base = 0; base < deg; base += 32) {
        int n = min(32, deg - base);
        int myIdx = 0;
        float myMsk = 0.f;
        if (lane < n) {
            myIdx = psrc[beg + base + lane];
            myMsk = pmask[beg + base + lane];
        }
        for (int jb = 0; jb < n; jb += 4) {
            int cnt = min(4, n - jb);
            float4 h[4];
            float mv[4];
#pragma unroll
            for (int u = 0; u < 4; u++) {
                int s = __shfl_sync(0xffffffffu, myIdx, jb + u);
                mv[u] = __shfl_sync(0xffffffffu, myMsk, jb + u);
                if (u < cnt) h[u] = hs4[(size_t)s * 64 + chunk];
            }
#pragma unroll
            for (int u = 0; u < 4; u++) {
                if (u < cnt) {
                    float z, p;
                    z = h[u].x + hdv.x; z = z > 0.f ? z : 0.2f * z; p  = z * av.x;
                    z = h[u].y + hdv.y; z = z > 0.f ? z : 0.2f * z; p += z * av.y;
                    z = h[u].z + hdv.z; z = z > 0.f ? z : 0.2f * z; p += z * av.z;
                    z = h[u].w + hdv.w; z = z > 0.f ? z : 0.2f * z; p += z * av.w;
#pragma unroll
                    for (int off = 8; off; off >>= 1)
                        p += __shfl_xor_sync(0xffffffffu, p, off);
                    float w = __expf(p) * mv[u];
                    den += w;
                    num.x += w * h[u].x; num.y += w * h[u].y;
                    num.z += w * h[u].z; num.w += w * h[u].w;
                }
            }
        }
    }

    float r = 1.f / (den + 1e-16f);
    float4 o = make_float4(num.x * r, num.y * r, num.z * r, num.w * r);
    if (doRelu) {
        o.x = fmaxf(o.x, 0.f); o.y = fmaxf(o.y, 0.f);
        o.z = fmaxf(o.z, 0.f); o.w = fmaxf(o.w, 0.f);
    }
    ((float4*)out)[(size_t)dst * 64 + chunk] = o;
}

// ---------------- pooling ---------------------------------------------------
__global__ void colsum_kernel(const float* __restrict__ X, float* __restrict__ sum256, int M) {
    float acc = 0.f;
    int c = threadIdx.x;
    for (int r = blockIdx.x; r < M; r += gridDim.x)
        acc += X[(size_t)r * HCV + c];
    atomicAdd(&sum256[c], acc);
}

// ---------------- finalize --------------------------------------------------
__global__ void finalize_kernel(const float* __restrict__ colsumArr, const float* __restrict__ agg,
                                const float* __restrict__ Wcls, const float* __restrict__ bcls,
                                float* __restrict__ out, int Nt, int T) {
    __shared__ float s[HCV];
    int c = threadIdx.x;
    s[c] = (colsumArr[c] / (float)Nt) * Wcls[c];
    __syncthreads();
    for (int o = 128; o; o >>= 1) {
        if (c < o) s[c] += s[c + o];
        __syncthreads();
    }
    if (c == 0) {
        float tot = s[0];
        for (int t = 0; t < T; t++) tot += agg[t] * Wcls[HCV + t];
        tot += bcls[0];
        out[0] = 1.f / (1.f + expf(-tot));
    }
}

// ---------------------------------------------------------------------------
extern "C" void kernel_launch(void* const* d_in, const int* in_sizes, int n_in,
                              void* d_out, int out_size) {
    const float* x_src     = (const float*)d_in[0];
    const float* x_tgt     = (const float*)d_in[1];
    const float* edge_attr = (const float*)d_in[2];
    const float* node_mask = (const float*)d_in[3];
    const float* edge_mask = (const float*)d_in[4];
    const int*   edge_index= (const int*)  d_in[5];
    const float* W1_src    = (const float*)d_in[6];
    const float* W1_dst    = (const float*)d_in[7];
    const float* a1        = (const float*)d_in[8];
    const float* W2_src    = (const float*)d_in[9];
    const float* W2_dst    = (const float*)d_in[10];
    const float* a2        = (const float*)d_in[11];
    const float* W_cls     = (const float*)d_in[12];
    const float* b_cls     = (const float*)d_in[13];

    const int Ns = in_sizes[3];
    const int E  = in_sizes[4];
    const int F  = in_sizes[0] / Ns;            // 128
    const int T  = in_sizes[2] / E;             // 6
    const int Nt = in_sizes[1] / (T * F);       // 20000
    const int t  = T - 1;

    float *hs1, *hd1, *h1, *hs2, *hd2, *h2, *pmask;
    int *rowoff, *cursor, *psrc;
    ZeroRegion* zr;
    cudaGetSymbolAddress((void**)&hs1, g_hs1);
    cudaGetSymbolAddress((void**)&hd1, g_hd1);
    cudaGetSymbolAddress((void**)&h1,  g_h1);
    cudaGetSymbolAddress((void**)&hs2, g_hs2);
    cudaGetSymbolAddress((void**)&hd2, g_hd2);
    cudaGetSymbolAddress((void**)&h2,  g_h2);
    cudaGetSymbolAddress((void**)&rowoff, g_rowoff);
    cudaGetSymbolAddress((void**)&cursor, g_cursor);
    cudaGetSymbolAddress((void**)&psrc,   g_psrc);
    cudaGetSymbolAddress((void**)&pmask,  g_pmask);
    cudaGetSymbolAddress((void**)&zr,     g_zero);
    int*   counts = zr->counts;
    float* csum   = zr->csum;
    float* agg    = zr->agg;

    const float* xt5  = x_tgt + (size_t)t * Nt * F;
    const int*   src5 = edge_index + (size_t)t * 2 * E;
    const int*   dst5 = src5 + E;
    const float* W1s5 = W1_src + (size_t)t * F * HCV;
    const float* W1d5 = W1_dst + (size_t)t * F * HCV;
    const float* a1_5 = a1 + (size_t)t * HCV;
    const float* W2s5 = W2_src + (size_t)t * F * HCV;
    const float* W2d5 = W2_dst + (size_t)t * HCV * HCV;
    const float* a2_5 = a2 + (size_t)t * HCV;

    int egrid = (E + 255) / 256;
    int ablocks = (Nt * 2 + 7) / 8;

    // launch order: attn1 must be launch #6 (ncu -s 5 -c 1 profiles it)
    cudaMemsetAsync(zr, 0, sizeof(ZeroRegion), 0);                                 // 1
    hist_kernel<<<egrid, 256>>>(dst5, counts, E);                                  // 2
    scan_kernel<<<1, 1024>>>(counts, rowoff, cursor, Nt);                          // 3
    scatter_kernel<<<egrid, 256>>>(src5, dst5, edge_mask, cursor, psrc, pmask, E); // 4

    dim3 g3((Ns + 127) / 128, 4, 2);
    gemm3_kernel<<<g3, 256>>>(x_src, W1s5, W2s5, hs1, hs2,
                              xt5, W1d5, hd1, node_mask, Ns, F);                   // 5

    attn_kernel<<<ablocks, 256>>>(hs1, hd1, a1_5, psrc, pmask, rowoff, h1, Nt, 1); // 6 <- profiled

    dim3 gT((Nt + 127) / 128, 2);
    gemm_tf32_kernel<<<gT, 256>>>(h1, W2d5, hd2, nullptr, Nt, HCV);                // 7
    attn_kernel<<<ablocks, 256>>>(hs2, hd2, a2_5, psrc, pmask, rowoff, h2, Nt, 0); // 8

    edge_mean_kernel<<<T * 32, 256>>>(edge_attr, agg, E);                          // 9
    colsum_kernel<<<256, 256>>>(h2, csum, Nt);                                     // 10
    finalize_kernel<<<1, 256>>>(csum, agg, W_cls, b_cls, (float*)d_out, Nt, T);    // 11
}